// round 1
// baseline (speedup 1.0000x reference)
#include <cuda_runtime.h>

#define Bn 4
#define Cn 256
#define Nn 131072          // D*H*W = 32*64*64
#define NVEC (Nn / 4)      // 32768 float4 per (b)
#define Kk 256
#define CAP 10240          // shared candidate buffer capacity

// ---------------- device scratch (static globals; no allocation) ------------
__device__ float4   g_scores4[Bn * NVEC];   // 2 MiB of scores
__device__ unsigned g_T[Bn];                // 32-bit threshold key per batch
__device__ int      g_rem[Bn];              // #ties at threshold still needed
__device__ int      g_cgt[Bn];              // selection counters (zeroed in radix kernel)
__device__ int      g_ceq[Bn];
__device__ int      g_topk[Bn * Kk];        // selected voxel indices

// monotone float->uint key: larger float => larger key
__device__ __forceinline__ unsigned fkey(float f) {
    unsigned u = __float_as_uint(f);
    return (u & 0x80000000u) ? ~u : (u | 0x80000000u);
}

// ---------------- kernel 1: per-voxel score (HBM-bound, 512 MiB read) -------
__global__ void score_kernel(const float4* __restrict__ F,
                             const float*  __restrict__ w) {
    __shared__ float sw[Cn];
    for (int i = threadIdx.x; i < Cn; i += blockDim.x) sw[i] = w[i];
    __syncthreads();

    int v = blockIdx.x * blockDim.x + threadIdx.x;   // [0, Bn*NVEC)
    if (v >= Bn * NVEC) return;
    int b  = v / NVEC;
    int nv = v - b * NVEC;
    const float4* base = F + (size_t)b * Cn * NVEC + nv;

    float ax = 0.f, ay = 0.f, az = 0.f, aw = 0.f;
#pragma unroll 4
    for (int c = 0; c < Cn; c++) {
        float4 x = __ldg(&base[(size_t)c * NVEC]);
        float wc = sw[c];
        ax = fmaf(x.x, wc, ax);
        ay = fmaf(x.y, wc, ay);
        az = fmaf(x.z, wc, az);
        aw = fmaf(x.w, wc, aw);
    }
    g_scores4[v] = make_float4(ax, ay, az, aw);
}

// ---------------- kernel 2: exact radix-select of k-th largest key ----------
// 1 block per batch, 1024 threads. MSB byte over global (warp-aggregated
// atomics), then compact candidates to shared and finish 3 levels in smem.
__global__ void radix_kernel() {
    const int b = blockIdx.x;
    const float* s = (const float*)g_scores4 + (size_t)b * Nn;

    __shared__ unsigned hist[256];
    __shared__ unsigned buf[CAP];
    __shared__ int s_cnt, s_cnt2, s_kk;
    __shared__ unsigned s_sel;

    const int t = threadIdx.x, nt = blockDim.x;

    // ---- level 3 (MSB byte) histogram over all N, warp-aggregated ----
    for (int i = t; i < 256; i += nt) hist[i] = 0;
    __syncthreads();
    for (int i = t; i < Nn; i += nt) {          // Nn % nt == 0: warps stay full
        unsigned bin  = fkey(s[i]) >> 24;
        unsigned mask = __match_any_sync(0xffffffffu, bin);
        if ((t & 31) == (__ffs(mask) - 1))
            atomicAdd(&hist[bin], (unsigned)__popc(mask));
    }
    __syncthreads();
    if (t == 0) {
        unsigned kk = Kk, cum = 0; int sel = 255;
        for (int bin = 255; bin >= 0; bin--) {
            unsigned h = hist[bin];
            if (cum + h >= kk) { sel = bin; break; }
            cum += h;
        }
        s_sel = (unsigned)sel;
        s_kk  = (int)(kk - cum);
        s_cnt = 0;
    }
    __syncthreads();
    unsigned prefix = s_sel << 24, pmask = 0xFF000000u;

    // ---- compact candidates of the straddling bin into shared ----
    for (int i = t; i < Nn; i += nt) {
        unsigned key = fkey(s[i]);
        if ((key & pmask) == prefix) {
            int p = atomicAdd(&s_cnt, 1);
            if (p < CAP) buf[p] = key;
        }
    }
    __syncthreads();
    int cnt = s_cnt;

    // ---- levels 2..0 ----
    for (int level = 2; level >= 0; level--) {
        __syncthreads();                         // protect s_cnt2 reuse
        for (int i = t; i < 256; i += nt) hist[i] = 0;
        if (t == 0) s_cnt2 = 0;
        __syncthreads();

        const int sh = 8 * level;
        if (cnt <= CAP) {
            for (int i = t; i < cnt; i += nt)
                atomicAdd(&hist[(buf[i] >> sh) & 255], 1u);
        } else {                                  // fallback: rescan global
            for (int i = t; i < Nn; i += nt) {
                unsigned key = fkey(s[i]);
                if ((key & pmask) == prefix)
                    atomicAdd(&hist[(key >> sh) & 255], 1u);
            }
        }
        __syncthreads();
        if (t == 0) {
            unsigned kk = (unsigned)s_kk, cum = 0; int sel = 255;
            for (int bin = 255; bin >= 0; bin--) {
                unsigned h = hist[bin];
                if (cum + h >= kk) { sel = bin; break; }
                cum += h;
            }
            s_sel = (unsigned)sel;
            s_kk  = (int)(kk - cum);
        }
        __syncthreads();
        prefix |= s_sel << sh;
        pmask  |= 0xFFu << sh;

        if (level > 0) {
            if (cnt <= CAP) {                    // in-place shared compaction
                unsigned local[(CAP + 1023) / 1024];
                int lc = 0;
                for (int i = t; i < cnt; i += nt) {
                    unsigned key = buf[i];
                    if ((key & pmask) == prefix) local[lc++] = key;
                }
                __syncthreads();
                for (int j = 0; j < lc; j++) {
                    int p = atomicAdd(&s_cnt2, 1);
                    buf[p] = local[j];
                }
                __syncthreads();
                cnt = s_cnt2;
            } else {                             // fallback compaction
                for (int i = t; i < Nn; i += nt) {
                    unsigned key = fkey(s[i]);
                    if ((key & pmask) == prefix) {
                        int p = atomicAdd(&s_cnt2, 1);
                        if (p < CAP) buf[p] = key;
                    }
                }
                __syncthreads();
                cnt = s_cnt2;
            }
        }
    }

    if (t == 0) {
        g_T[b]   = prefix;
        g_rem[b] = s_kk;
        g_cgt[b] = 0;     // reset selection counters inside the graph
        g_ceq[b] = 0;
    }
}

// ---------------- kernel 3: collect exactly K indices per batch -------------
__global__ void select_kernel() {
    int i = blockIdx.x * blockDim.x + threadIdx.x;
    if (i >= Bn * Nn) return;
    const float* s = (const float*)g_scores4;
    int b = i >> 17;             // /Nn
    int n = i & (Nn - 1);
    unsigned key = fkey(s[i]);
    unsigned T   = g_T[b];
    if (key > T) {
        int p = atomicAdd(&g_cgt[b], 1);
        g_topk[b * Kk + p] = n;
    } else if (key == T) {
        int e = atomicAdd(&g_ceq[b], 1);
        int rem = g_rem[b];
        if (e < rem) g_topk[b * Kk + (Kk - rem) + e] = n;
    }
}

// ---------------- kernel 4: gather selected voxels + mean over K ------------
__global__ void gather_kernel(const float* __restrict__ F,
                              float* __restrict__ out) {
    int c = blockIdx.x;
    int b = blockIdx.y;
    int j = threadIdx.x;                         // 256 threads == K

    int idx = g_topk[b * Kk + j];
    float v = __ldg(&F[((size_t)(b * Cn + c)) * Nn + idx]);

#pragma unroll
    for (int o = 16; o; o >>= 1) v += __shfl_down_sync(0xffffffffu, v, o);

    __shared__ float red[8];
    if ((j & 31) == 0) red[j >> 5] = v;
    __syncthreads();
    if (j == 0) {
        float sum = 0.f;
#pragma unroll
        for (int q = 0; q < 8; q++) sum += red[q];
        out[b * Cn + c] = sum * (1.0f / Kk);
    }
}

// ---------------- launcher ---------------------------------------------------
extern "C" void kernel_launch(void* const* d_in, const int* in_sizes, int n_in,
                              void* d_out, int out_size) {
    const float4* F  = (const float4*)d_in[0];
    const float*  w  = (const float*)d_in[1];
    float*        out = (float*)d_out;

    score_kernel<<<(Bn * NVEC + 255) / 256, 256>>>(F, w);
    radix_kernel<<<Bn, 1024>>>();
    select_kernel<<<(Bn * Nn + 255) / 256, 256>>>();
    gather_kernel<<<dim3(Cn, Bn), 256>>>((const float*)d_in[0], out);
}

// round 2
// speedup vs baseline: 1.3277x; 1.3277x over previous
#include <cuda_runtime.h>

#define Bn 4
#define Cn 256
#define Nn 131072          // D*H*W
#define NVEC (Nn / 4)      // 32768 float4 per batch
#define Kk 256
#define CCAP 32768         // per-batch candidate capacity (expected ~2.9K)

// ---------------- device scratch (static globals; no allocation) ------------
__device__ float4   g_scores4[Bn * NVEC];   // 2 MiB scores
__device__ unsigned g_hist[Bn * 256];       // MSB-byte histograms (self-reset)
__device__ unsigned g_selbin[Bn];           // straddling MSB bin
__device__ int      g_kk[Bn];               // K minus higher-bin count
__device__ int      g_cgt[Bn];              // g_topk fill counter
__device__ int      g_ccand[Bn];            // candidate count
__device__ uint2    g_cand[Bn * CCAP];      // (key, voxel idx) in straddling bin
__device__ int      g_topk[Bn * Kk];

// monotone float->uint key: larger float => larger key
__device__ __forceinline__ unsigned fkey(float f) {
    unsigned u = __float_as_uint(f);
    return (u & 0x80000000u) ? ~u : (u | 0x80000000u);
}

// ---------------- kernel 1: score + fused MSB histogram ---------------------
__global__ void score_kernel(const float4* __restrict__ F,
                             const float*  __restrict__ w) {
    __shared__ float sw[Cn];
    __shared__ unsigned hist[256];
    for (int i = threadIdx.x; i < Cn; i += blockDim.x) sw[i] = w[i];
    for (int i = threadIdx.x; i < 256; i += blockDim.x) hist[i] = 0;
    __syncthreads();

    int v  = blockIdx.x * blockDim.x + threadIdx.x;   // [0, Bn*NVEC)
    int b  = v >> 15;                                  // / NVEC
    int nv = v & (NVEC - 1);
    const float4* base = F + (size_t)b * Cn * NVEC + nv;

    float ax = 0.f, ay = 0.f, az = 0.f, aw = 0.f;
#pragma unroll 8
    for (int c = 0; c < Cn; c++) {
        float4 x = __ldg(&base[(size_t)c * NVEC]);
        float wc = sw[c];
        ax = fmaf(x.x, wc, ax);
        ay = fmaf(x.y, wc, ay);
        az = fmaf(x.z, wc, az);
        aw = fmaf(x.w, wc, aw);
    }
    g_scores4[v] = make_float4(ax, ay, az, aw);

    // warp-aggregated shared histogram of the 4 MSB bytes
    unsigned kb[4] = { fkey(ax) >> 24, fkey(ay) >> 24, fkey(az) >> 24, fkey(aw) >> 24 };
    const int lane = threadIdx.x & 31;
#pragma unroll
    for (int j = 0; j < 4; j++) {
        unsigned mask = __match_any_sync(0xffffffffu, kb[j]);
        if (lane == (__ffs(mask) - 1))
            atomicAdd(&hist[kb[j]], (unsigned)__popc(mask));
    }
    __syncthreads();
    unsigned* gh = g_hist + b * 256;   // all threads in block share b
    for (int i = threadIdx.x; i < 256; i += blockDim.x)
        if (hist[i]) atomicAdd(&gh[i], hist[i]);
}

// ---------------- kernel 2: pick straddling bin, reset state ----------------
__global__ void scan_kernel() {
    const int b = blockIdx.x, t = threadIdx.x;
    __shared__ unsigned h[256];
    h[t] = g_hist[b * 256 + t];
    g_hist[b * 256 + t] = 0;          // self-reset for next graph replay
    __syncthreads();
    if (t == 0) {
        unsigned cum = 0; int sel = 255;
        for (int bin = 255; bin >= 0; bin--) {
            unsigned c = h[bin];
            if (cum + c >= Kk) { sel = bin; break; }
            cum += c;
        }
        g_selbin[b] = (unsigned)sel;
        g_kk[b]     = Kk - (int)cum;
        g_cgt[b]    = 0;
        g_ccand[b]  = 0;
    }
}

// ---------------- kernel 3: compact high bins + candidates ------------------
__global__ void compact_kernel() {
    int v  = blockIdx.x * blockDim.x + threadIdx.x;   // float4 index
    int b  = v >> 15;
    int nv = v & (NVEC - 1);
    float4 s = g_scores4[v];
    unsigned sel = g_selbin[b];
    float sv[4] = { s.x, s.y, s.z, s.w };
#pragma unroll
    for (int j = 0; j < 4; j++) {
        unsigned key = fkey(sv[j]);
        unsigned bin = key >> 24;
        int n = nv * 4 + j;
        if (bin > sel) {
            int p = atomicAdd(&g_cgt[b], 1);          // guaranteed < Kk
            g_topk[b * Kk + p] = n;
        } else if (bin == sel) {
            int p = atomicAdd(&g_ccand[b], 1);
            if (p < CCAP) g_cand[b * CCAP + p] = make_uint2(key, (unsigned)n);
        }
    }
}

// ---------------- kernel 4: refine 3 radix levels on candidates -------------
__global__ void finish_kernel() {
    const int b = blockIdx.x, t = threadIdx.x, nt = blockDim.x;
    const int cnt = g_ccand[b];
    const bool fb = (cnt > CCAP);                    // fallback: rescan global
    const uint2* cand = g_cand + b * CCAP;
    const float* sc = (const float*)g_scores4 + (size_t)b * Nn;
    const unsigned selbin = g_selbin[b];

    __shared__ unsigned hist[256];
    __shared__ unsigned s_sel;
    __shared__ int s_kk, s_eq;

    unsigned prefix = selbin << 24, pmask = 0xFF000000u;
    int kk = g_kk[b];

    for (int level = 2; level >= 0; level--) {
        for (int i = t; i < 256; i += nt) hist[i] = 0;
        __syncthreads();
        const int sh = 8 * level;
        if (!fb) {
            for (int i = t; i < cnt; i += nt) {
                unsigned key = cand[i].x;
                if ((key & pmask) == prefix)
                    atomicAdd(&hist[(key >> sh) & 255], 1u);
            }
        } else {
            for (int i = t; i < Nn; i += nt) {
                unsigned key = fkey(sc[i]);
                if ((key & pmask) == prefix)
                    atomicAdd(&hist[(key >> sh) & 255], 1u);
            }
        }
        __syncthreads();
        if (t == 0) {
            unsigned cum = 0; int sel = 255;
            for (int bin = 255; bin >= 0; bin--) {
                unsigned h = hist[bin];
                if (cum + h >= (unsigned)kk) { sel = bin; break; }
                cum += h;
            }
            s_sel = (unsigned)sel;
            s_kk  = kk - (int)cum;
        }
        __syncthreads();
        prefix |= s_sel << sh;
        pmask  |= 0xFFu << sh;
        kk = s_kk;
        __syncthreads();
    }

    const unsigned T = prefix;
    const int rem = kk;                // ties at T still needed
    if (t == 0) s_eq = 0;
    __syncthreads();

    if (!fb) {
        for (int i = t; i < cnt; i += nt) {
            uint2 c = cand[i];
            if (c.x > T) {
                int p = atomicAdd(&g_cgt[b], 1);
                g_topk[b * Kk + p] = (int)c.y;
            } else if (c.x == T) {
                int e = atomicAdd(&s_eq, 1);
                if (e < rem) g_topk[b * Kk + (Kk - rem) + e] = (int)c.y;
            }
        }
    } else {
        for (int i = t; i < Nn; i += nt) {
            unsigned key = fkey(sc[i]);
            if ((key >> 24) == selbin) {
                if (key > T) {
                    int p = atomicAdd(&g_cgt[b], 1);
                    g_topk[b * Kk + p] = i;
                } else if (key == T) {
                    int e = atomicAdd(&s_eq, 1);
                    if (e < rem) g_topk[b * Kk + (Kk - rem) + e] = i;
                }
            }
        }
    }
}

// ---------------- kernel 5: gather 8 channels/block + mean ------------------
__global__ void gather_kernel(const float* __restrict__ F,
                              float* __restrict__ out) {
    const int b  = blockIdx.y;
    const int c0 = blockIdx.x * 8;
    const int j  = threadIdx.x;                       // 256 == K

    const int idx = g_topk[b * Kk + j];
    const float* base = F + ((size_t)(b * Cn + c0)) * Nn + idx;

    float v[8];
#pragma unroll
    for (int u = 0; u < 8; u++) v[u] = __ldg(&base[(size_t)u * Nn]);

    __shared__ float red[8][8];
#pragma unroll
    for (int u = 0; u < 8; u++) {
        float s = v[u];
#pragma unroll
        for (int o = 16; o; o >>= 1) s += __shfl_down_sync(0xffffffffu, s, o);
        if ((j & 31) == 0) red[u][j >> 5] = s;
    }
    __syncthreads();
    if (j < 8) {
        float s = 0.f;
#pragma unroll
        for (int q = 0; q < 8; q++) s += red[j][q];
        out[b * Cn + c0 + j] = s * (1.0f / Kk);
    }
}

// ---------------- launcher ---------------------------------------------------
extern "C" void kernel_launch(void* const* d_in, const int* in_sizes, int n_in,
                              void* d_out, int out_size) {
    const float4* F  = (const float4*)d_in[0];
    const float*  w  = (const float*)d_in[1];
    float*        out = (float*)d_out;

    score_kernel  <<<Bn * NVEC / 256, 256>>>(F, w);
    scan_kernel   <<<Bn, 256>>>();
    compact_kernel<<<Bn * NVEC / 256, 256>>>();
    finish_kernel <<<Bn, 1024>>>();
    gather_kernel <<<dim3(Cn / 8, Bn), 256>>>((const float*)d_in[0], out);
}

// round 3
// speedup vs baseline: 1.5021x; 1.1314x over previous
#include <cuda_runtime.h>

#define Bn 4
#define Cn 256
#define Nn 131072          // D*H*W
#define NVEC (Nn / 4)      // 32768 float4 per batch
#define Kk 256
#define CCAP 32768         // per-batch candidate capacity (expected ~2.9K)

// ---------------- device scratch (static globals; no allocation) ------------
__device__ float4   g_scores4[Bn * NVEC];   // 2 MiB scores
__device__ unsigned g_hist[Bn * 256];       // MSB-byte histograms (self-reset)
__device__ unsigned g_selbin[Bn];           // straddling MSB bin
__device__ int      g_kk[Bn];               // K minus higher-bin count
__device__ int      g_cgt[Bn];              // g_topk fill counter
__device__ int      g_ccand[Bn];            // candidate count
__device__ uint2    g_cand[Bn * CCAP];      // (key, voxel idx) in straddling bin
__device__ int      g_topk[Bn * Kk];

// monotone float->uint key: larger float => larger key
__device__ __forceinline__ unsigned fkey(float f) {
    unsigned u = __float_as_uint(f);
    return (u & 0x80000000u) ? ~u : (u | 0x80000000u);
}

// Warp-parallel selection of straddling bin (call from full warp 0).
// h[256] in shared; finds max bin with inclusive-from-top suffix >= kk.
// Writes bin to *out_sel and the remaining count to *out_kk (shared).
__device__ __forceinline__ void select_bin_warp(const unsigned* __restrict__ h,
                                                int kk,
                                                unsigned* out_sel, int* out_kk) {
    const int lane = threadIdx.x & 31;
    unsigned loc[8];
    unsigned chunk = 0;
#pragma unroll
    for (int j = 0; j < 8; j++) { loc[j] = h[lane * 8 + j]; chunk += loc[j]; }
    // inclusive prefix over lanes (low->high)
    unsigned pref = chunk;
#pragma unroll
    for (int o = 1; o < 32; o <<= 1) {
        unsigned v = __shfl_up_sync(0xffffffffu, pref, o);
        if (lane >= o) pref += v;
    }
    unsigned total = __shfl_sync(0xffffffffu, pref, 31);
    unsigned above = total - pref;          // sum over lanes > lane
    unsigned cum = above;                   // count strictly above current bin
#pragma unroll
    for (int j = 7; j >= 0; j--) {
        unsigned nc = cum + loc[j];
        if (cum < (unsigned)kk && nc >= (unsigned)kk) {
            *out_sel = (unsigned)(lane * 8 + j);
            *out_kk  = kk - (int)cum;
        }
        cum = nc;
    }
}

// ---------------- kernel 1: score + fused MSB histogram ---------------------
__global__ void score_kernel(const float4* __restrict__ F,
                             const float*  __restrict__ w) {
    __shared__ float sw[Cn];
    __shared__ unsigned hist[256];
    for (int i = threadIdx.x; i < Cn; i += blockDim.x) sw[i] = w[i];
    for (int i = threadIdx.x; i < 256; i += blockDim.x) hist[i] = 0;
    __syncthreads();

    int v  = blockIdx.x * blockDim.x + threadIdx.x;   // [0, Bn*NVEC)
    int b  = v >> 15;                                  // / NVEC
    int nv = v & (NVEC - 1);
    const float4* base = F + (size_t)b * Cn * NVEC + nv;

    float ax = 0.f, ay = 0.f, az = 0.f, aw = 0.f;
#pragma unroll 8
    for (int c = 0; c < Cn; c++) {
        float4 x = __ldg(&base[(size_t)c * NVEC]);
        float wc = sw[c];
        ax = fmaf(x.x, wc, ax);
        ay = fmaf(x.y, wc, ay);
        az = fmaf(x.z, wc, az);
        aw = fmaf(x.w, wc, aw);
    }
    g_scores4[v] = make_float4(ax, ay, az, aw);

    // warp-aggregated shared histogram of the 4 MSB bytes
    unsigned kb[4] = { fkey(ax) >> 24, fkey(ay) >> 24, fkey(az) >> 24, fkey(aw) >> 24 };
    const int lane = threadIdx.x & 31;
#pragma unroll
    for (int j = 0; j < 4; j++) {
        unsigned mask = __match_any_sync(0xffffffffu, kb[j]);
        if (lane == (__ffs(mask) - 1))
            atomicAdd(&hist[kb[j]], (unsigned)__popc(mask));
    }
    __syncthreads();
    unsigned* gh = g_hist + b * 256;   // all threads in block share b
    for (int i = threadIdx.x; i < 256; i += blockDim.x)
        if (hist[i]) atomicAdd(&gh[i], hist[i]);
}

// ---------------- kernel 2: pick straddling MSB bin, reset state ------------
__global__ void scan_kernel() {
    const int b = blockIdx.x, t = threadIdx.x;
    __shared__ unsigned h[256];
    __shared__ unsigned s_sel;
    __shared__ int s_kk;
    h[t] = g_hist[b * 256 + t];
    g_hist[b * 256 + t] = 0;          // self-reset for next graph replay
    __syncthreads();
    if (t < 32) select_bin_warp(h, Kk, &s_sel, &s_kk);
    __syncthreads();
    if (t == 0) {
        g_selbin[b] = s_sel;
        g_kk[b]     = s_kk;
        g_cgt[b]    = 0;
        g_ccand[b]  = 0;
    }
}

// ---------------- kernel 3: compact high bins + candidates ------------------
__global__ void compact_kernel() {
    int v  = blockIdx.x * blockDim.x + threadIdx.x;   // float4 index
    int b  = v >> 15;
    int nv = v & (NVEC - 1);
    float4 s = g_scores4[v];
    unsigned sel = g_selbin[b];
    float sv[4] = { s.x, s.y, s.z, s.w };
#pragma unroll
    for (int j = 0; j < 4; j++) {
        unsigned key = fkey(sv[j]);
        unsigned bin = key >> 24;
        int n = nv * 4 + j;
        if (bin > sel) {
            int p = atomicAdd(&g_cgt[b], 1);          // guaranteed < Kk
            g_topk[b * Kk + p] = n;
        } else if (bin == sel) {
            int p = atomicAdd(&g_ccand[b], 1);
            if (p < CCAP) g_cand[b * CCAP + p] = make_uint2(key, (unsigned)n);
        }
    }
}

// ---------------- kernel 4: refine 3 radix levels on candidates -------------
__global__ void finish_kernel() {
    const int b = blockIdx.x, t = threadIdx.x, nt = blockDim.x;
    const int cnt = g_ccand[b];
    const bool fb = (cnt > CCAP);                    // fallback: rescan global
    const uint2* cand = g_cand + b * CCAP;
    const float* sc = (const float*)g_scores4 + (size_t)b * Nn;
    const unsigned selbin = g_selbin[b];

    __shared__ unsigned hist[256];
    __shared__ unsigned s_sel;
    __shared__ int s_kk, s_eq;

    unsigned prefix = selbin << 24, pmask = 0xFF000000u;
    int kk = g_kk[b];

    for (int level = 2; level >= 0; level--) {
        for (int i = t; i < 256; i += nt) hist[i] = 0;
        __syncthreads();
        const int sh = 8 * level;
        if (!fb) {
            for (int i = t; i < cnt; i += nt) {
                unsigned key = cand[i].x;
                if ((key & pmask) == prefix)
                    atomicAdd(&hist[(key >> sh) & 255], 1u);
            }
        } else {
            for (int i = t; i < Nn; i += nt) {
                unsigned key = fkey(sc[i]);
                if ((key & pmask) == prefix)
                    atomicAdd(&hist[(key >> sh) & 255], 1u);
            }
        }
        __syncthreads();
        if (t < 32) select_bin_warp(hist, kk, &s_sel, &s_kk);
        __syncthreads();
        prefix |= s_sel << sh;
        pmask  |= 0xFFu << sh;
        kk = s_kk;
        __syncthreads();
    }

    const unsigned T = prefix;
    const int rem = kk;                // ties at T still needed
    if (t == 0) s_eq = 0;
    __syncthreads();

    if (!fb) {
        for (int i = t; i < cnt; i += nt) {
            uint2 c = cand[i];
            if (c.x > T) {
                int p = atomicAdd(&g_cgt[b], 1);
                g_topk[b * Kk + p] = (int)c.y;
            } else if (c.x == T) {
                int e = atomicAdd(&s_eq, 1);
                if (e < rem) g_topk[b * Kk + (Kk - rem) + e] = (int)c.y;
            }
        }
    } else {
        for (int i = t; i < Nn; i += nt) {
            unsigned key = fkey(sc[i]);
            if ((key >> 24) == selbin) {
                if (key > T) {
                    int p = atomicAdd(&g_cgt[b], 1);
                    g_topk[b * Kk + p] = i;
                } else if (key == T) {
                    int e = atomicAdd(&s_eq, 1);
                    if (e < rem) g_topk[b * Kk + (Kk - rem) + e] = i;
                }
            }
        }
    }
}

// ---------------- kernel 5: gather 8 channels/block + mean ------------------
__global__ void gather_kernel(const float* __restrict__ F,
                              float* __restrict__ out) {
    const int b  = blockIdx.y;
    const int c0 = blockIdx.x * 8;
    const int j  = threadIdx.x;                       // 256 == K

    const int idx = g_topk[b * Kk + j];
    const float* base = F + ((size_t)(b * Cn + c0)) * Nn + idx;

    float v[8];
#pragma unroll
    for (int u = 0; u < 8; u++) v[u] = __ldg(&base[(size_t)u * Nn]);

    __shared__ float red[8][8];
#pragma unroll
    for (int u = 0; u < 8; u++) {
        float s = v[u];
#pragma unroll
        for (int o = 16; o; o >>= 1) s += __shfl_down_sync(0xffffffffu, s, o);
        if ((j & 31) == 0) red[u][j >> 5] = s;
    }
    __syncthreads();
    if (j < 8) {
        float s = 0.f;
#pragma unroll
        for (int q = 0; q < 8; q++) s += red[j][q];
        out[b * Cn + c0 + j] = s * (1.0f / Kk);
    }
}

// ---------------- launcher ---------------------------------------------------
extern "C" void kernel_launch(void* const* d_in, const int* in_sizes, int n_in,
                              void* d_out, int out_size) {
    const float4* F  = (const float4*)d_in[0];
    const float*  w  = (const float*)d_in[1];
    float*        out = (float*)d_out;

    score_kernel  <<<Bn * NVEC / 256, 256>>>(F, w);
    scan_kernel   <<<Bn, 256>>>();
    compact_kernel<<<Bn * NVEC / 256, 256>>>();
    finish_kernel <<<Bn, 512>>>();
    gather_kernel <<<dim3(Cn / 8, Bn), 256>>>((const float*)d_in[0], out);
}

// round 4
// speedup vs baseline: 1.5725x; 1.0468x over previous
#include <cuda_runtime.h>

#define Bn 4
#define Cn 256
#define Nn 131072          // D*H*W
#define NVEC (Nn / 4)      // 32768 float4 per batch
#define Kk 256
#define CCAP 32768         // per-batch global candidate capacity
#define FCAP 6144          // shared key capacity in finish (expected ~2.9K)
#define FNT 512            // finish block size

// ---------------- device scratch (static globals; no allocation) ------------
__device__ float4   g_scores4[Bn * NVEC];   // 2 MiB scores
__device__ unsigned g_hist[Bn * 256];       // MSB-byte histograms (self-reset)
__device__ unsigned g_selbin[Bn];           // straddling MSB bin
__device__ int      g_kk[Bn];               // K minus higher-bin count
__device__ int      g_cgt[Bn];              // g_topk fill counter
__device__ int      g_ccand[Bn];            // candidate count
__device__ uint2    g_cand[Bn * CCAP];      // (key, voxel idx) in straddling bin
__device__ int      g_topk[Bn * Kk];

// monotone float->uint key: larger float => larger key
__device__ __forceinline__ unsigned fkey(float f) {
    unsigned u = __float_as_uint(f);
    return (u & 0x80000000u) ? ~u : (u | 0x80000000u);
}

// Warp-parallel straddling-bin selection over 32*NPL entries (descending index
// = higher rank). Finds max index i with (count of entries > i) < kk <= (+h[i]).
template<int NPL>
__device__ __forceinline__ void warp_select(const unsigned* __restrict__ h,
                                            int kk, unsigned* out_idx, int* out_kk) {
    const int lane = threadIdx.x & 31;
    unsigned loc[NPL];
    unsigned chunk = 0;
#pragma unroll
    for (int j = 0; j < NPL; j++) { loc[j] = h[lane * NPL + j]; chunk += loc[j]; }
    unsigned pref = chunk;                       // inclusive prefix low->high lane
#pragma unroll
    for (int o = 1; o < 32; o <<= 1) {
        unsigned v = __shfl_up_sync(0xffffffffu, pref, o);
        if (lane >= o) pref += v;
    }
    unsigned total = __shfl_sync(0xffffffffu, pref, 31);
    unsigned cum = total - pref;                 // entries in higher lanes
#pragma unroll
    for (int j = NPL - 1; j >= 0; j--) {
        unsigned nc = cum + loc[j];
        if (cum < (unsigned)kk && nc >= (unsigned)kk) {
            *out_idx = (unsigned)(lane * NPL + j);
            *out_kk  = kk - (int)cum;
        }
        cum = nc;
    }
}

// ---------------- kernel 1: score + fused MSB histogram ---------------------
__global__ void score_kernel(const float4* __restrict__ F,
                             const float*  __restrict__ w) {
    __shared__ float sw[Cn];
    __shared__ unsigned hist[256];
    for (int i = threadIdx.x; i < Cn; i += blockDim.x) sw[i] = w[i];
    for (int i = threadIdx.x; i < 256; i += blockDim.x) hist[i] = 0;
    __syncthreads();

    int v  = blockIdx.x * blockDim.x + threadIdx.x;   // [0, Bn*NVEC)
    int b  = v >> 15;                                  // / NVEC
    int nv = v & (NVEC - 1);
    const float4* base = F + (size_t)b * Cn * NVEC + nv;

    float ax = 0.f, ay = 0.f, az = 0.f, aw = 0.f;
#pragma unroll 8
    for (int c = 0; c < Cn; c++) {
        float4 x = __ldcs(&base[(size_t)c * NVEC]);   // streaming: no reuse
        float wc = sw[c];
        ax = fmaf(x.x, wc, ax);
        ay = fmaf(x.y, wc, ay);
        az = fmaf(x.z, wc, az);
        aw = fmaf(x.w, wc, aw);
    }
    g_scores4[v] = make_float4(ax, ay, az, aw);

    unsigned kb[4] = { fkey(ax) >> 24, fkey(ay) >> 24, fkey(az) >> 24, fkey(aw) >> 24 };
    const int lane = threadIdx.x & 31;
#pragma unroll
    for (int j = 0; j < 4; j++) {
        unsigned mask = __match_any_sync(0xffffffffu, kb[j]);
        if (lane == (__ffs(mask) - 1))
            atomicAdd(&hist[kb[j]], (unsigned)__popc(mask));
    }
    __syncthreads();
    unsigned* gh = g_hist + b * 256;
    for (int i = threadIdx.x; i < 256; i += blockDim.x)
        if (hist[i]) atomicAdd(&gh[i], hist[i]);
}

// ---------------- kernel 2: pick straddling MSB bin, reset state ------------
__global__ void scan_kernel() {
    const int b = blockIdx.x, t = threadIdx.x;
    __shared__ unsigned h[256];
    __shared__ unsigned s_sel;
    __shared__ int s_kk;
    h[t] = g_hist[b * 256 + t];
    g_hist[b * 256 + t] = 0;          // self-reset for next graph replay
    __syncthreads();
    if (t < 32) warp_select<8>(h, Kk, &s_sel, &s_kk);
    __syncthreads();
    if (t == 0) {
        g_selbin[b] = s_sel;
        g_kk[b]     = s_kk;
        g_cgt[b]    = 0;
        g_ccand[b]  = 0;
    }
}

// ---------------- kernel 3: compact high bins + candidates ------------------
__global__ void compact_kernel() {
    int v  = blockIdx.x * blockDim.x + threadIdx.x;   // float4 index
    int b  = v >> 15;
    int nv = v & (NVEC - 1);
    float4 s = g_scores4[v];
    unsigned sel = g_selbin[b];
    float sv[4] = { s.x, s.y, s.z, s.w };
#pragma unroll
    for (int j = 0; j < 4; j++) {
        unsigned key = fkey(sv[j]);
        unsigned bin = key >> 24;
        int n = nv * 4 + j;
        if (bin > sel) {
            int p = atomicAdd(&g_cgt[b], 1);          // guaranteed < Kk
            g_topk[b * Kk + p] = n;
        } else if (bin == sel) {
            int p = atomicAdd(&g_ccand[b], 1);
            if (p < CCAP) g_cand[b * CCAP + p] = make_uint2(key, (unsigned)n);
        }
    }
}

// ---------------- kernel 4: resolve threshold on candidates -----------------
__global__ void finish_kernel() {
    const int b = blockIdx.x, t = threadIdx.x;
    const int cnt_raw = g_ccand[b];
    const int cnt = cnt_raw < CCAP ? cnt_raw : CCAP;
    const uint2* cand = g_cand + b * CCAP;
    const float* sc = (const float*)g_scores4 + (size_t)b * Nn;
    const unsigned selbin = g_selbin[b];

    __shared__ unsigned skey[FCAP];      // 24 KB
    __shared__ unsigned hist[4096];      // 16 KB
    __shared__ unsigned partial[FNT];    //  2 KB
    __shared__ unsigned s_idx;
    __shared__ int s_kk, s_eq;

    unsigned T;                          // final 32-bit threshold key
    int rem;                             // ties at T still needed
    int kk = g_kk[b];

    if (cnt_raw <= FCAP) {
        // ---------- fast path: keys in shared, two 12-bit levels ----------
        for (int i = t; i < 4096; i += FNT) hist[i] = 0;
        __syncthreads();
        for (int i = t; i < cnt; i += FNT) {
            unsigned key = cand[i].x;
            skey[i] = key;
            atomicAdd(&hist[(key >> 12) & 4095], 1u);
        }
        __syncthreads();

        unsigned bin12;
        // two-stage selection over 4096 bins
        {
            unsigned p = 0;
#pragma unroll
            for (int j = 0; j < 8; j++) p += hist[t * 8 + j];
            partial[t] = p;
            __syncthreads();
            if (t < 32) warp_select<16>(partial, kk, &s_idx, &s_kk);
            __syncthreads();
            if (t == 0) {                            // walk the 8 bins of the chunk
                int base = (int)s_idx * 8, k2 = s_kk;
                unsigned cum = 0, selb = 0;
                for (int j = 7; j >= 0; j--) {
                    unsigned h = hist[base + j];
                    if (cum < (unsigned)k2 && cum + h >= (unsigned)k2) {
                        selb = (unsigned)(base + j);
                        s_kk = k2 - (int)cum;
                    }
                    cum += h;
                }
                s_idx = selb;
            }
            __syncthreads();
            bin12 = s_idx; kk = s_kk;
        }
        __syncthreads();

        // level B: bits[11:0] among keys matching bin12
        for (int i = t; i < 4096; i += FNT) hist[i] = 0;
        __syncthreads();
        for (int i = t; i < cnt; i += FNT) {
            unsigned key = skey[i];
            if (((key >> 12) & 4095) == bin12)
                atomicAdd(&hist[key & 4095], 1u);
        }
        __syncthreads();
        {
            unsigned p = 0;
#pragma unroll
            for (int j = 0; j < 8; j++) p += hist[t * 8 + j];
            partial[t] = p;
            __syncthreads();
            if (t < 32) warp_select<16>(partial, kk, &s_idx, &s_kk);
            __syncthreads();
            if (t == 0) {
                int base = (int)s_idx * 8, k2 = s_kk;
                unsigned cum = 0, selb = 0;
                for (int j = 7; j >= 0; j--) {
                    unsigned h = hist[base + j];
                    if (cum < (unsigned)k2 && cum + h >= (unsigned)k2) {
                        selb = (unsigned)(base + j);
                        s_kk = k2 - (int)cum;
                    }
                    cum += h;
                }
                s_idx = selb;
            }
            __syncthreads();
        }
        T = (selbin << 24) | (bin12 << 12) | s_idx;
        rem = s_kk;
    } else {
        // ---------- fallback: 3x 8-bit levels (global candidate reads) ----
        const bool fb = (cnt_raw > CCAP);
        unsigned prefix = selbin << 24, pmask = 0xFF000000u;
        for (int level = 2; level >= 0; level--) {
            for (int i = t; i < 256; i += FNT) hist[i] = 0;
            __syncthreads();
            const int sh = 8 * level;
            if (!fb) {
                for (int i = t; i < cnt; i += FNT) {
                    unsigned key = cand[i].x;
                    if ((key & pmask) == prefix)
                        atomicAdd(&hist[(key >> sh) & 255], 1u);
                }
            } else {
                for (int i = t; i < Nn; i += FNT) {
                    unsigned key = fkey(sc[i]);
                    if ((key & pmask) == prefix)
                        atomicAdd(&hist[(key >> sh) & 255], 1u);
                }
            }
            __syncthreads();
            if (t < 32) warp_select<8>(hist, kk, &s_idx, &s_kk);
            __syncthreads();
            prefix |= s_idx << sh;
            pmask  |= 0xFFu << sh;
            kk = s_kk;
            __syncthreads();
        }
        T = prefix;
        rem = kk;
    }

    if (t == 0) s_eq = 0;
    __syncthreads();

    if (cnt_raw <= CCAP) {
        for (int i = t; i < cnt; i += FNT) {
            uint2 c = cand[i];
            if (c.x > T) {
                int p = atomicAdd(&g_cgt[b], 1);
                g_topk[b * Kk + p] = (int)c.y;
            } else if (c.x == T) {
                int e = atomicAdd(&s_eq, 1);
                if (e < rem) g_topk[b * Kk + (Kk - rem) + e] = (int)c.y;
            }
        }
    } else {
        for (int i = t; i < Nn; i += FNT) {
            unsigned key = fkey(sc[i]);
            if ((key >> 24) == selbin) {
                if (key > T) {
                    int p = atomicAdd(&g_cgt[b], 1);
                    g_topk[b * Kk + p] = i;
                } else if (key == T) {
                    int e = atomicAdd(&s_eq, 1);
                    if (e < rem) g_topk[b * Kk + (Kk - rem) + e] = i;
                }
            }
        }
    }
}

// ---------------- kernel 5: gather 8 channels/block + mean ------------------
__global__ void gather_kernel(const float* __restrict__ F,
                              float* __restrict__ out) {
    const int b  = blockIdx.y;
    const int c0 = blockIdx.x * 8;
    const int j  = threadIdx.x;                       // 256 == K

    const int idx = g_topk[b * Kk + j];
    const float* base = F + ((size_t)(b * Cn + c0)) * Nn + idx;

    float v[8];
#pragma unroll
    for (int u = 0; u < 8; u++) v[u] = __ldg(&base[(size_t)u * Nn]);

    __shared__ float red[8][8];
#pragma unroll
    for (int u = 0; u < 8; u++) {
        float s = v[u];
#pragma unroll
        for (int o = 16; o; o >>= 1) s += __shfl_down_sync(0xffffffffu, s, o);
        if ((j & 31) == 0) red[u][j >> 5] = s;
    }
    __syncthreads();
    if (j < 8) {
        float s = 0.f;
#pragma unroll
        for (int q = 0; q < 8; q++) s += red[j][q];
        out[b * Cn + c0 + j] = s * (1.0f / Kk);
    }
}

// ---------------- launcher ---------------------------------------------------
extern "C" void kernel_launch(void* const* d_in, const int* in_sizes, int n_in,
                              void* d_out, int out_size) {
    const float4* F  = (const float4*)d_in[0];
    const float*  w  = (const float*)d_in[1];
    float*        out = (float*)d_out;

    score_kernel  <<<Bn * NVEC / 256, 256>>>(F, w);
    scan_kernel   <<<Bn, 256>>>();
    compact_kernel<<<Bn * NVEC / 256, 256>>>();
    finish_kernel <<<Bn, FNT>>>();
    gather_kernel <<<dim3(Cn / 8, Bn), 256>>>((const float*)d_in[0], out);
}